// round 4
// baseline (speedup 1.0000x reference)
#include <cuda_runtime.h>
#include <stdint.h>

// Hash-grid trilinear interpolation, hash-sorted for L2 locality.
//
// Key insight: corner bucket = (h + const_c) & MASK where h = base hash.
// Processing points in ascending-h order turns all 8 gather streams into
// ascending sweeps of the table -> each 128B table line read ~once from DRAM
// (~128MB) instead of 16M random 32B sectors (~512MB).
//
// Pipeline: zero-hist -> histogram(h>>9) -> scan -> scatter {xyz,idx} -> interp.
// Scan rebuilds offsets every replay, so scatter's atomicAdd mutation is
// replay-safe. Out written via original idx; result order-independent.

#define BUCKETS_MASK ((1u << 22) - 1u)
#define P1 1u
#define P2 2654435761u
#define P3 805459861u

#define NBINS 8192          // 2^13 bins over 2^22 buckets -> 512 buckets/bin
#define BIN_SHIFT 9         // 22 - 13
#define MAX_PTS 2100000

__device__ float4 g_sorted[MAX_PTS];    // {x, y, z, idx-as-float-bits}
__device__ int    g_hist[NBINS];
__device__ int    g_off[NBINS];

__device__ __forceinline__ uint32_t base_hash(float x, float y, float z) {
    float qx = x * 1024.0f, qy = y * 1024.0f, qz = z * 1024.0f;
    uint32_t bx = (uint32_t)(int)floorf(qx);
    uint32_t by = (uint32_t)(int)floorf(qy);
    uint32_t bz = (uint32_t)(int)floorf(qz);
    return bx * P1 + by * P2 + bz * P3;
}

__global__ void k_zero_hist() {
    int i = blockIdx.x * blockDim.x + threadIdx.x;
    if (i < NBINS) g_hist[i] = 0;
}

__global__ void __launch_bounds__(256) k_hist(const float* __restrict__ pts, int n) {
    int i = blockIdx.x * blockDim.x + threadIdx.x;
    if (i >= n) return;
    float x = __ldcs(pts + 3 * i + 0);
    float y = __ldcs(pts + 3 * i + 1);
    float z = __ldcs(pts + 3 * i + 2);
    uint32_t bin = (base_hash(x, y, z) & BUCKETS_MASK) >> BIN_SHIFT;
    atomicAdd(&g_hist[bin], 1);
}

// Single-block exclusive scan over NBINS (8192) with 1024 threads, 8 bins each.
__global__ void __launch_bounds__(1024) k_scan() {
    __shared__ int sh[1024];
    int t = threadIdx.x;
    int local[8];
    int sum = 0;
#pragma unroll
    for (int j = 0; j < 8; j++) {
        local[j] = g_hist[t * 8 + j];
        sum += local[j];
    }
    sh[t] = sum;
    __syncthreads();
    // Hillis-Steele inclusive scan over 1024 partials
    for (int d = 1; d < 1024; d <<= 1) {
        int v = (t >= d) ? sh[t - d] : 0;
        __syncthreads();
        sh[t] += v;
        __syncthreads();
    }
    int base = sh[t] - sum;   // exclusive prefix for this thread's chunk
    int run = base;
#pragma unroll
    for (int j = 0; j < 8; j++) {
        g_off[t * 8 + j] = run;
        run += local[j];
    }
}

__global__ void __launch_bounds__(256) k_scatter(const float* __restrict__ pts, int n) {
    int i = blockIdx.x * blockDim.x + threadIdx.x;
    if (i >= n) return;
    float x = __ldcs(pts + 3 * i + 0);
    float y = __ldcs(pts + 3 * i + 1);
    float z = __ldcs(pts + 3 * i + 2);
    uint32_t bin = (base_hash(x, y, z) & BUCKETS_MASK) >> BIN_SHIFT;
    int pos = atomicAdd(&g_off[bin], 1);
    g_sorted[pos] = make_float4(x, y, z, __int_as_float(i));
}

__global__ void __launch_bounds__(256) k_interp(
    const float4* __restrict__ vf,   // (BUCKETS, 8 fp32) = 2x float4 per bucket
    float4* __restrict__ out,        // (N, 8 fp32) = 2x float4 per point
    int n)
{
    int i = blockIdx.x * blockDim.x + threadIdx.x;
    if (i >= n) return;

    float4 p = g_sorted[i];          // coalesced 128B
    int oi = __float_as_int(p.w);

    float qx = p.x * 1024.0f, qy = p.y * 1024.0f, qz = p.z * 1024.0f;
    float bxf = floorf(qx), byf = floorf(qy), bzf = floorf(qz);
    float fx = qx - bxf, fy = qy - byf, fz = qz - bzf;

    uint32_t bx = (uint32_t)(int)bxf;
    uint32_t by = (uint32_t)(int)byf;
    uint32_t bz = (uint32_t)(int)bzf;
    uint32_t h  = bx * P1 + by * P2 + bz * P3;

    uint32_t vid[8];
    vid[0] = (h)                & BUCKETS_MASK;
    vid[1] = (h + P1)           & BUCKETS_MASK;
    vid[2] = (h + P2)           & BUCKETS_MASK;
    vid[3] = (h + P1 + P2)      & BUCKETS_MASK;
    vid[4] = (h + P3)           & BUCKETS_MASK;
    vid[5] = (h + P1 + P3)      & BUCKETS_MASK;
    vid[6] = (h + P2 + P3)      & BUCKETS_MASK;
    vid[7] = (h + P1 + P2 + P3) & BUCKETS_MASK;

    float gx = 1.0f - fx, gy = 1.0f - fy, gz = 1.0f - fz;
    float w[8];
    w[0] = gx * gy * gz;  w[1] = fx * gy * gz;
    w[2] = gx * fy * gz;  w[3] = fx * fy * gz;
    w[4] = gx * gy * fz;  w[5] = fx * gy * fz;
    w[6] = gx * fy * fz;  w[7] = fx * fy * fz;

    float4 f0[8], f1[8];
#pragma unroll
    for (int c = 0; c < 8; c++) {
        const float4* q = vf + (size_t)vid[c] * 2;
        f0[c] = __ldg(q);
        f1[c] = __ldg(q + 1);
    }

    float4 a0 = make_float4(0.f, 0.f, 0.f, 0.f);
    float4 a1 = make_float4(0.f, 0.f, 0.f, 0.f);
#pragma unroll
    for (int c = 0; c < 8; c++) {
        float wc = w[c];
        a0.x = fmaf(wc, f0[c].x, a0.x);
        a0.y = fmaf(wc, f0[c].y, a0.y);
        a0.z = fmaf(wc, f0[c].z, a0.z);
        a0.w = fmaf(wc, f0[c].w, a0.w);
        a1.x = fmaf(wc, f1[c].x, a1.x);
        a1.y = fmaf(wc, f1[c].y, a1.y);
        a1.z = fmaf(wc, f1[c].z, a1.z);
        a1.w = fmaf(wc, f1[c].w, a1.w);
    }

    __stcs(out + 2 * (size_t)oi + 0, a0);
    __stcs(out + 2 * (size_t)oi + 1, a1);
}

// Fallback (unsorted) in case n exceeds static scratch capacity.
__global__ void __launch_bounds__(256) k_interp_direct(
    const float* __restrict__ pts, const float4* __restrict__ vf,
    float4* __restrict__ out, int n)
{
    int i = blockIdx.x * blockDim.x + threadIdx.x;
    if (i >= n) return;
    float x = pts[3*i], y = pts[3*i+1], z = pts[3*i+2];
    float qx = x*1024.f, qy = y*1024.f, qz = z*1024.f;
    float bxf = floorf(qx), byf = floorf(qy), bzf = floorf(qz);
    float fx = qx-bxf, fy = qy-byf, fz = qz-bzf;
    uint32_t h = (uint32_t)(int)bxf*P1 + (uint32_t)(int)byf*P2 + (uint32_t)(int)bzf*P3;
    uint32_t vid[8] = {(h)&BUCKETS_MASK,(h+P1)&BUCKETS_MASK,(h+P2)&BUCKETS_MASK,(h+P1+P2)&BUCKETS_MASK,
                       (h+P3)&BUCKETS_MASK,(h+P1+P3)&BUCKETS_MASK,(h+P2+P3)&BUCKETS_MASK,(h+P1+P2+P3)&BUCKETS_MASK};
    float gx=1.f-fx, gy=1.f-fy, gz=1.f-fz;
    float w[8] = {gx*gy*gz, fx*gy*gz, gx*fy*gz, fx*fy*gz, gx*gy*fz, fx*gy*fz, gx*fy*fz, fx*fy*fz};
    float4 a0 = make_float4(0,0,0,0), a1 = make_float4(0,0,0,0);
#pragma unroll
    for (int c = 0; c < 8; c++) {
        float4 u0 = __ldg(vf + (size_t)vid[c]*2);
        float4 u1 = __ldg(vf + (size_t)vid[c]*2 + 1);
        float wc = w[c];
        a0.x=fmaf(wc,u0.x,a0.x); a0.y=fmaf(wc,u0.y,a0.y); a0.z=fmaf(wc,u0.z,a0.z); a0.w=fmaf(wc,u0.w,a0.w);
        a1.x=fmaf(wc,u1.x,a1.x); a1.y=fmaf(wc,u1.y,a1.y); a1.z=fmaf(wc,u1.z,a1.z); a1.w=fmaf(wc,u1.w,a1.w);
    }
    out[2*(size_t)i] = a0; out[2*(size_t)i+1] = a1;
}

extern "C" void kernel_launch(void* const* d_in, const int* in_sizes, int n_in,
                              void* d_out, int out_size)
{
    const float*  pts = (const float*)d_in[0];
    const float4* vf  = (const float4*)d_in[1];
    float4* out = (float4*)d_out;
    int n = in_sizes[0] / 3;

    if (n > MAX_PTS) {
        k_interp_direct<<<(n + 255) / 256, 256>>>(pts, vf, out, n);
        return;
    }

    int gb = (n + 255) / 256;
    k_zero_hist<<<(NBINS + 255) / 256, 256>>>();
    k_hist<<<gb, 256>>>(pts, n);
    k_scan<<<1, 1024>>>();
    k_scatter<<<gb, 256>>>(pts, n);
    k_interp<<<gb, 256>>>(vf, out, n);
}

// round 5
// speedup vs baseline: 1.5532x; 1.5532x over previous
#include <cuda_runtime.h>
#include <stdint.h>

// Hash-grid trilinear interpolation — warp-cooperative gathers + partial L2 pin.
//
// 1) Coop layout (kills the L1tex wavefront floor): P1=1 so corner pairs
//    (2p,2p+1) are adjacent buckets = 64 contiguous bytes. 4 lanes per pair,
//    16 lanes per point, warp = 2 points/round. shfl.xor reduction.
// 2) Partial pinning (kills DRAM bytes): table slice vid < PIN_LIMIT (96MB of
//    the 128MB table) is loaded with L2::evict_last; the other 25% slice and
//    all streaming traffic use evict_first. Pinned set < L2 capacity, so it
//    stays resident across graph replays -> steady-state gather DRAM ~128MB.

#define BUCKETS_MASK ((1u << 22) - 1u)
#define P1 1u
#define P2 2654435761u
#define P3 805459861u
#define PIN_LIMIT (3u << 20)      // 3/4 of 2^22 buckets = 96 MB pinned

__device__ __forceinline__ uint64_t mk_policy_evict_last() {
    uint64_t pol;
    asm("createpolicy.fractional.L2::evict_last.b64 %0, 1.0;" : "=l"(pol));
    return pol;
}
__device__ __forceinline__ uint64_t mk_policy_evict_first() {
    uint64_t pol;
    asm("createpolicy.fractional.L2::evict_first.b64 %0, 1.0;" : "=l"(pol));
    return pol;
}

__device__ __forceinline__ float4 ldg_hint(const void* p, uint64_t pol) {
    float4 v;
    asm("ld.global.nc.L2::cache_hint.v4.f32 {%0,%1,%2,%3}, [%4], %5;"
        : "=f"(v.x), "=f"(v.y), "=f"(v.z), "=f"(v.w)
        : "l"(p), "l"(pol));
    return v;
}

template <int U>
__global__ void __launch_bounds__(256) hashgrid_coop_pin_kernel(
    const float* __restrict__ pts,   // (N,3)
    const char*  __restrict__ vf,    // (BUCKETS, 8 fp32) = 32 B per bucket
    float4*      __restrict__ out,   // (N, 8 fp32) = 2 float4 per point
    int n)
{
    int warp_g = (blockIdx.x * blockDim.x + threadIdx.x) >> 5;
    int lane   = threadIdx.x & 31;
    int l      = lane & 15;          // lane within 16-lane point-group
    int group  = lane >> 4;          // which of the warp's 2 points this round

    int pair = l >> 2;               // corner pair 0..3
    int j    = l & 3;                // float4 slot within the 64B pair block
    int c    = 2 * pair + (j >> 1);  // corner index 0..7
    uint32_t cx = (uint32_t)(c & 1);
    uint32_t cy = (uint32_t)((c >> 1) & 1);
    uint32_t cz = (uint32_t)((c >> 2) & 1);
    uint32_t hoff = cx * P1 + cy * P2 + cz * P3;

    uint64_t pol_last  = mk_policy_evict_last();
    uint64_t pol_first = mk_policy_evict_first();

    int base = warp_g * (2 * U);

    float4 f[U];
    float  wgt[U];
    int    idx[U];
    bool   valid[U];

#pragma unroll
    for (int r = 0; r < U; r++) {
        int i = base + 2 * r + group;
        idx[r]   = i;
        valid[r] = (i < n);
        int ii = valid[r] ? i : 0;

        // broadcast load of the point (16 lanes same addr -> merged wavefront)
        float x = __ldcs(pts + 3 * ii + 0);
        float y = __ldcs(pts + 3 * ii + 1);
        float z = __ldcs(pts + 3 * ii + 2);

        float qx = x * 1024.0f, qy = y * 1024.0f, qz = z * 1024.0f;
        float bxf = floorf(qx), byf = floorf(qy), bzf = floorf(qz);
        float fx = qx - bxf, fy = qy - byf, fz = qz - bzf;

        uint32_t bx = (uint32_t)(int)bxf;
        uint32_t by = (uint32_t)(int)byf;
        uint32_t bz = (uint32_t)(int)bzf;
        uint32_t h  = bx * P1 + by * P2 + bz * P3;

        uint32_t vid = (h + hoff) & BUCKETS_MASK;
        const char* ptr = vf + ((size_t)vid << 5) + ((uint32_t)(j & 1) << 4);
        uint64_t pol = (vid < PIN_LIMIT) ? pol_last : pol_first;
        f[r] = ldg_hint(ptr, pol);       // U independent gathers in flight

        float wx = cx ? fx : 1.0f - fx;
        float wy = cy ? fy : 1.0f - fy;
        float wz = cz ? fz : 1.0f - fz;
        wgt[r] = wx * wy * wz;
    }

#pragma unroll
    for (int r = 0; r < U; r++) {
        float4 v;
        v.x = wgt[r] * f[r].x;
        v.y = wgt[r] * f[r].y;
        v.z = wgt[r] * f[r].z;
        v.w = wgt[r] * f[r].w;

        // butterfly sum over the 8 lanes holding the same half (j parity)
#pragma unroll
        for (int m = 2; m <= 8; m <<= 1) {
            v.x += __shfl_xor_sync(0xFFFFFFFFu, v.x, m);
            v.y += __shfl_xor_sync(0xFFFFFFFFu, v.y, m);
            v.z += __shfl_xor_sync(0xFFFFFFFFu, v.z, m);
            v.w += __shfl_xor_sync(0xFFFFFFFFu, v.w, m);
        }

        // lane 0 = out_lo, lane 1 = out_hi (per group)
        if (l < 2 && valid[r]) {
            __stcs(out + 2 * (size_t)idx[r] + l, v);
        }
    }
}

extern "C" void kernel_launch(void* const* d_in, const int* in_sizes, int n_in,
                              void* d_out, int out_size)
{
    const float* pts = (const float*)d_in[0];
    const char*  vf  = (const char*)d_in[1];
    float4*      out = (float4*)d_out;

    int n = in_sizes[0] / 3;

    constexpr int U = 4;                 // points-per-warp = 2*U = 8
    long long warps   = ((long long)n + (2 * U) - 1) / (2 * U);
    long long threads = warps * 32;
    int block = 256;
    long long grid = (threads + block - 1) / block;

    hashgrid_coop_pin_kernel<U><<<(int)grid, block>>>(pts, vf, out, n);
}